// round 8
// baseline (speedup 1.0000x reference)
#include <cuda_runtime.h>
#include <stdint.h>
#include <math.h>

// Problem constants
#define B_TOTAL 8192
#define T_STEPS 60
#define F_IN    158
#define HDIM    32
#define G4      128
#define NBLK    128                    // 64-row batch tiles for xg layout
#define TPAIRS  30

typedef unsigned long long u64;
typedef ulonglong2 u64x2;

// 251.7 MB scratch: xg[tile][m(64)][n(128)], tile = t*NBLK + blk
__device__ __align__(256) float g_xg[(size_t)T_STEPS * NBLK * 64 * G4];

// ---------------- helpers ----------------
__device__ __forceinline__ void ffma2(u64 &acc, u64 a, u64 b) {
    asm("fma.rn.f32x2 %0, %1, %2, %0;" : "+l"(acc) : "l"(a), "l"(b));
}
__device__ __forceinline__ u64 pack2s(float x) {
    u64 r; asm("mov.b64 %0, {%1, %1};" : "=l"(r) : "f"(x)); return r;
}
__device__ __forceinline__ float2 unpack2(u64 v) {
    float2 r; asm("mov.b64 {%0, %1}, %2;" : "=f"(r.x), "=f"(r.y) : "l"(v)); return r;
}
__device__ __forceinline__ float tanha(float x) {
    float y; asm("tanh.approx.f32 %0, %1;" : "=f"(y) : "f"(x)); return y;
}
__device__ __forceinline__ float sigf(float x) {      // 0.5*tanh(x/2)+0.5
    return fmaf(0.5f, tanha(0.5f * x), 0.5f);
}
__device__ __forceinline__ void cp_async16(uint32_t dst, const void* src) {
    asm volatile("cp.async.cg.shared.global [%0], [%1], 16;" :: "r"(dst), "l"(src));
}
__device__ __forceinline__ void cp_commit()  { asm volatile("cp.async.commit_group;"); }
__device__ __forceinline__ void cp_waitall() { asm volatile("cp.async.wait_group 0;" ::: "memory"); }

__device__ __forceinline__ uint32_t tf32_of(float x) {
    uint32_t r; asm("cvt.rna.tf32.f32 %0, %1;" : "=r"(r) : "f"(x)); return r;
}
// D(m16n8) += A(m16k8,row) * B(k8n8,col) ; tf32 inputs in b32 regs, f32 accum
__device__ __forceinline__ void mma_tf32(float d[4],
                                         uint32_t a0, uint32_t a1, uint32_t a2, uint32_t a3,
                                         uint32_t b0, uint32_t b1) {
    asm volatile(
        "mma.sync.aligned.m16n8k8.row.col.f32.tf32.tf32.f32 "
        "{%0,%1,%2,%3}, {%4,%5,%6,%7}, {%8,%9}, {%0,%1,%2,%3};"
        : "+f"(d[0]), "+f"(d[1]), "+f"(d[2]), "+f"(d[3])
        : "r"(a0), "r"(a1), "r"(a2), "r"(a3), "r"(b0), "r"(b1));
}

// =======================================================================
// Kernel A: xg = x @ W_ih0^T via tensor cores (split-precision tf32).
//   item = (tp, hb): 32 batch rows (hb*32..+32), timesteps 2tp, 2tp+1.
//   x smem: [32][320] fp32, XOR-4 k-swizzle (conflict-free A-frag loads).
//   W smem: hi/lo tf32-valued fp32, [n][160] with XOR-4 k-swizzle.
//   Warp w owns m32 x n16 (ntiles 2w, 2w+1). 8 warps cover n=128.
//   xg = xh@Wh + xh@Wl + xl@Wh  (~fp32 accuracy).
// =======================================================================
#define A_THREADS 256
#define XROW      320
#define A_ITEMS   (TPAIRS * 256)          // 7680
#define SW_FLOATS (G4 * 160)              // 20480 per precision
#define A_SMEM_BYTES ((2 * SW_FLOATS + 32 * XROW) * 4)   // 204800 B

__device__ __forceinline__ void a_copy(const float* __restrict__ x,
                                       int item, float* xb, int tid) {
    int tp = item >> 8;
    int hb = item & 255;
    const char* sb = (const char*)x + (size_t)hb * 32 * (F_IN * T_STEPS * 4)
                                    + (size_t)tp * 1264;   // 2*158*4, 16B aligned
    uint32_t db = (uint32_t)__cvta_generic_to_shared(xb);
    for (int i = tid; i < 32 * 79; i += A_THREADS) {
        int r = i / 79, c = i - r * 79;
        int cs = c ^ (r & 7);                              // 16B-chunk swizzle
        cp_async16(db + r * (XROW * 4) + 16 * cs,
                   sb + (size_t)r * (F_IN * T_STEPS * 4) + 16 * c);
    }
}

__global__ void __launch_bounds__(A_THREADS)
xg_kernel(const float* __restrict__ x, const float* __restrict__ Wih0) {
    extern __shared__ float sm[];
    float* sWh = sm;                      // [128][160] swizzled, tf32-hi
    float* sWl = sm + SW_FLOATS;          // tf32-lo
    float* xb  = sm + 2 * SW_FLOATS;      // [32][320] swizzled fp32

    const int tid = threadIdx.x;
    const int lane = tid & 31, w = tid >> 5;
    const int g = lane >> 2, tq = lane & 3;
    const int swz = 4 * g;

    // ---- weight prep: split fp32 -> tf32 hi + lo, swizzled store ----
    for (int i = tid; i < G4 * 160; i += A_THREADS) {
        int n = i / 160, k = i - n * 160;
        float v = (k < F_IN) ? Wih0[n * F_IN + k] : 0.0f;
        uint32_t hbits = tf32_of(v);
        float hf = __uint_as_float(hbits);
        uint32_t lbits = tf32_of(v - hf);
        int idx = n * 160 + (k ^ (4 * (n & 7)));
        sWh[idx] = hf;
        sWl[idx] = __uint_as_float(lbits);
    }
    // zero the never-written k-chunk (k=316..319 in k-space) of each x row
    if (tid < 32) {
        int p = (79 ^ (tid & 7)) * 4;
        float* row = xb + tid * XROW;
        row[p] = 0.f; row[p + 1] = 0.f; row[p + 2] = 0.f; row[p + 3] = 0.f;
    }

    // per-lane pointers
    const float* r0 = xb + (g)      * XROW;
    const float* r1 = xb + (g + 8)  * XROW;
    const float* r2 = xb + (g + 16) * XROW;
    const float* r3 = xb + (g + 24) * XROW;
    const int nA = 16 * w + g;                 // b-col for ntile 2w
    const float* bh0p = sWh + nA * 160;
    const float* bl0p = sWl + nA * 160;
    const float* bh1p = bh0p + 8 * 160;        // ntile 2w+1
    const float* bl1p = bl0p + 8 * 160;

    for (int item = blockIdx.x; item < A_ITEMS; item += gridDim.x) {
        a_copy(x, item, xb, tid);
        cp_commit();
        cp_waitall();
        __syncthreads();                       // x + weights resident

        const int tp = item >> 8, hb = item & 255;
        const int blk = hb >> 1, half = hb & 1;

#pragma unroll
        for (int sub = 0; sub < 2; ++sub) {
            const int koff = sub * F_IN;
            float acc[4][4];                   // [mt*2+ntl][4]
#pragma unroll
            for (int q = 0; q < 4; ++q)
#pragma unroll
                for (int p = 0; p < 4; ++p) acc[q][p] = 0.0f;

#pragma unroll 4
            for (int kt = 0; kt < 20; ++kt) {
                int kk = koff + 8 * kt + tq;
                int iA0 = kk ^ swz;
                int iA1 = (kk + 4) ^ swz;
                // A frags (8 fp32) -> hi/lo tf32
                float f0 = r0[iA0], f1 = r1[iA0], f2 = r0[iA1], f3 = r1[iA1];
                float f4 = r2[iA0], f5 = r3[iA0], f6 = r2[iA1], f7 = r3[iA1];
                uint32_t ah[2][4], al[2][4];
                ah[0][0] = tf32_of(f0); al[0][0] = tf32_of(f0 - __uint_as_float(ah[0][0]));
                ah[0][1] = tf32_of(f1); al[0][1] = tf32_of(f1 - __uint_as_float(ah[0][1]));
                ah[0][2] = tf32_of(f2); al[0][2] = tf32_of(f2 - __uint_as_float(ah[0][2]));
                ah[0][3] = tf32_of(f3); al[0][3] = tf32_of(f3 - __uint_as_float(ah[0][3]));
                ah[1][0] = tf32_of(f4); al[1][0] = tf32_of(f4 - __uint_as_float(ah[1][0]));
                ah[1][1] = tf32_of(f5); al[1][1] = tf32_of(f5 - __uint_as_float(ah[1][1]));
                ah[1][2] = tf32_of(f6); al[1][2] = tf32_of(f6 - __uint_as_float(ah[1][2]));
                ah[1][3] = tf32_of(f7); al[1][3] = tf32_of(f7 - __uint_as_float(ah[1][3]));

                int iB0 = (8 * kt + tq) ^ swz;
                int iB1 = (8 * kt + tq + 4) ^ swz;
                uint32_t bh[2][2], bl[2][2];
                bh[0][0] = __float_as_uint(bh0p[iB0]);
                bh[0][1] = __float_as_uint(bh0p[iB1]);
                bl[0][0] = __float_as_uint(bl0p[iB0]);
                bl[0][1] = __float_as_uint(bl0p[iB1]);
                bh[1][0] = __float_as_uint(bh1p[iB0]);
                bh[1][1] = __float_as_uint(bh1p[iB1]);
                bl[1][0] = __float_as_uint(bl1p[iB0]);
                bl[1][1] = __float_as_uint(bl1p[iB1]);

#pragma unroll
                for (int mt = 0; mt < 2; ++mt)
#pragma unroll
                    for (int ntl = 0; ntl < 2; ++ntl) {
                        float* a = acc[mt * 2 + ntl];
                        mma_tf32(a, ah[mt][0], ah[mt][1], ah[mt][2], ah[mt][3],
                                 bh[ntl][0], bh[ntl][1]);
                        mma_tf32(a, ah[mt][0], ah[mt][1], ah[mt][2], ah[mt][3],
                                 bl[ntl][0], bl[ntl][1]);
                        mma_tf32(a, al[mt][0], al[mt][1], al[mt][2], al[mt][3],
                                 bh[ntl][0], bh[ntl][1]);
                    }
            }

            // store D frags -> g_xg[t][blk][m64][n128]
            const int t = 2 * tp + sub;
            float* dstb = g_xg + ((size_t)t * NBLK + blk) * (64 * G4);
#pragma unroll
            for (int mt = 0; mt < 2; ++mt)
#pragma unroll
                for (int ntl = 0; ntl < 2; ++ntl) {
                    const float* a = acc[mt * 2 + ntl];
                    int mrow = half * 32 + mt * 16 + g;
                    int col  = 16 * w + 8 * ntl + 2 * tq;
                    float* d = dstb + (size_t)mrow * G4 + col;
                    *(float2*)d            = make_float2(a[0], a[1]);
                    *(float2*)(d + 8 * G4) = make_float2(a[2], a[3]);
                }
        }
        __syncthreads();                       // done reading xb before next copy
    }
}

// =======================================================================
// Kernel B: recurrence (unchanged from R6, measured 298 us).
// =======================================================================
#define B_THREADS 256
#define HPAD 68
#define B_SW  (HDIM * G4)                      // 4096 floats per matrix
#define B_SMEM_BYTES (3 * B_SW * 4 + 2 * HDIM * HPAD * 4)   // 66560 B

__global__ void __launch_bounds__(B_THREADS)
lstm_rec_kernel(const float* __restrict__ Whh0, const float* __restrict__ Wih1,
                const float* __restrict__ Whh1, const float* __restrict__ W1,
                const float* __restrict__ b1,   const float* __restrict__ W2,
                float* __restrict__ out) {
    extern __shared__ char smraw[];
    float* sW0 = (float*)smraw;                     // Whh0 [k][128]
    float* sW1 = sW0 + B_SW;                        // Wih1
    float* sW2 = sW1 + B_SW;                        // Whh1
    float* h1  = sW2 + B_SW;                        // [32][68]
    float* h2  = h1 + HDIM * HPAD;

    const int tid = threadIdx.x;
    const int j = tid & 31, wrp = tid >> 5;
    const int m0 = wrp * 8;                         // 8 warps x 8 rows
    const int blk = blockIdx.x;

    for (int i = tid; i < HDIM * G4; i += B_THREADS) {
        int k = i >> 7, n = i & 127;
        sW0[i] = Whh0[n * HDIM + k];
        sW1[i] = Wih1[n * HDIM + k];
        sW2[i] = Whh1[n * HDIM + k];
    }
    for (int i = tid; i < 2 * HDIM * HPAD; i += B_THREADS) h1[i] = 0.0f;
    __syncthreads();

    float c1[8], c2[8];
#pragma unroll
    for (int q = 0; q < 8; ++q) { c1[q] = 0.0f; c2[q] = 0.0f; }

    for (int t = 0; t < T_STEPS; ++t) {
        const float* xt = g_xg + ((size_t)t * NBLK + blk) * (64 * G4);
        float xr[4][8];                             // [g][row]
#pragma unroll
        for (int g = 0; g < 4; ++g)
#pragma unroll
            for (int q = 0; q < 8; ++q)
                xr[g][q] = __ldg(xt + (m0 + q) * G4 + j + 32 * g);

        // ---- layer 1: acc = h1 @ Whh0^T ----
        u64 acc[4][4];
#pragma unroll
        for (int g = 0; g < 4; ++g)
#pragma unroll
            for (int p = 0; p < 4; ++p) acc[g][p] = 0ULL;

#pragma unroll 4
        for (int k = 0; k < HDIM; ++k) {
            u64x2 ha = *(const u64x2*)(h1 + k * HPAD + m0);
            u64x2 hb = *(const u64x2*)(h1 + k * HPAD + m0 + 4);
            const float* wk = sW0 + k * G4 + j;
#pragma unroll
            for (int g = 0; g < 4; ++g) {
                u64 wv = pack2s(wk[32 * g]);
                ffma2(acc[g][0], ha.x, wv);
                ffma2(acc[g][1], ha.y, wv);
                ffma2(acc[g][2], hb.x, wv);
                ffma2(acc[g][3], hb.y, wv);
            }
        }

        float hn[8];
#pragma unroll
        for (int p = 0; p < 4; ++p) {
            float2 iv = unpack2(acc[0][p]);
            float2 fv = unpack2(acc[1][p]);
            float2 gv = unpack2(acc[2][p]);
            float2 ov = unpack2(acc[3][p]);
            iv.x += xr[0][2 * p]; iv.y += xr[0][2 * p + 1];
            fv.x += xr[1][2 * p]; fv.y += xr[1][2 * p + 1];
            gv.x += xr[2][2 * p]; gv.y += xr[2][2 * p + 1];
            ov.x += xr[3][2 * p]; ov.y += xr[3][2 * p + 1];
            float ca = sigf(fv.x) * c1[2 * p]     + sigf(iv.x) * tanha(gv.x);
            float cb = sigf(fv.y) * c1[2 * p + 1] + sigf(iv.y) * tanha(gv.y);
            c1[2 * p] = ca; c1[2 * p + 1] = cb;
            hn[2 * p]     = sigf(ov.x) * tanha(ca);
            hn[2 * p + 1] = sigf(ov.y) * tanha(cb);
        }
        __syncwarp();
        *(float4*)(h1 + j * HPAD + m0)     = make_float4(hn[0], hn[1], hn[2], hn[3]);
        *(float4*)(h1 + j * HPAD + m0 + 4) = make_float4(hn[4], hn[5], hn[6], hn[7]);
        __syncwarp();

        // ---- layer 2: acc = h1_new @ Wih1^T + h2 @ Whh1^T ----
#pragma unroll
        for (int g = 0; g < 4; ++g)
#pragma unroll
            for (int p = 0; p < 4; ++p) acc[g][p] = 0ULL;

#pragma unroll 4
        for (int k = 0; k < HDIM; ++k) {
            u64x2 ha = *(const u64x2*)(h1 + k * HPAD + m0);
            u64x2 hb = *(const u64x2*)(h1 + k * HPAD + m0 + 4);
            u64x2 ga = *(const u64x2*)(h2 + k * HPAD + m0);
            u64x2 gb = *(const u64x2*)(h2 + k * HPAD + m0 + 4);
            const float* wka = sW1 + k * G4 + j;
            const float* wkb = sW2 + k * G4 + j;
#pragma unroll
            for (int g = 0; g < 4; ++g) {
                u64 wa = pack2s(wka[32 * g]);
                u64 wb = pack2s(wkb[32 * g]);
                ffma2(acc[g][0], ha.x, wa);
                ffma2(acc[g][1], ha.y, wa);
                ffma2(acc[g][2], hb.x, wa);
                ffma2(acc[g][3], hb.y, wa);
                ffma2(acc[g][0], ga.x, wb);
                ffma2(acc[g][1], ga.y, wb);
                ffma2(acc[g][2], gb.x, wb);
                ffma2(acc[g][3], gb.y, wb);
            }
        }

#pragma unroll
        for (int p = 0; p < 4; ++p) {
            float2 iv = unpack2(acc[0][p]);
            float2 fv = unpack2(acc[1][p]);
            float2 gv = unpack2(acc[2][p]);
            float2 ov = unpack2(acc[3][p]);
            float ca = sigf(fv.x) * c2[2 * p]     + sigf(iv.x) * tanha(gv.x);
            float cb = sigf(fv.y) * c2[2 * p + 1] + sigf(iv.y) * tanha(gv.y);
            c2[2 * p] = ca; c2[2 * p + 1] = cb;
            hn[2 * p]     = sigf(ov.x) * tanha(ca);
            hn[2 * p + 1] = sigf(ov.y) * tanha(cb);
        }
        __syncwarp();
        *(float4*)(h2 + j * HPAD + m0)     = make_float4(hn[0], hn[1], hn[2], hn[3]);
        *(float4*)(h2 + j * HPAD + m0 + 4) = make_float4(hn[4], hn[5], hn[6], hn[7]);
        __syncwarp();
    }
    __syncthreads();

    // ---- epilogue: y = relu(c_n @ W1^T + b1) @ W2^T ----
    float* cs = (float*)smraw;
#pragma unroll
    for (int q = 0; q < 8; ++q) {
        cs[(m0 + q) * 33 + j]      = c1[q];
        cs[(64 + m0 + q) * 33 + j] = c2[q];
    }
    __syncthreads();

    if (tid < 128) {
        int L = tid >> 6, m = tid & 63;
        const float* crow = &cs[(L * 64 + m) * 33];
        float y = 0.0f;
#pragma unroll
        for (int u = 0; u < 16; ++u) {
            float s = __ldg(&b1[u]);
#pragma unroll
            for (int q = 0; q < 32; ++q) s += crow[q] * __ldg(&W1[u * 32 + q]);
            y += fmaxf(s, 0.0f) * __ldg(&W2[u]);
        }
        out[L * B_TOTAL + blk * 64 + m] = y;
    }
}

extern "C" void kernel_launch(void* const* d_in, const int* in_sizes, int n_in,
                              void* d_out, int out_size) {
    const float* x    = (const float*)d_in[0];
    const float* Wih0 = (const float*)d_in[1];
    const float* Whh0 = (const float*)d_in[2];
    const float* Wih1 = (const float*)d_in[3];
    const float* Whh1 = (const float*)d_in[4];
    const float* W1   = (const float*)d_in[5];
    const float* b1   = (const float*)d_in[6];
    const float* W2   = (const float*)d_in[7];
    float* out        = (float*)d_out;

    cudaFuncSetAttribute(xg_kernel, cudaFuncAttributeMaxDynamicSharedMemorySize, A_SMEM_BYTES);
    cudaFuncSetAttribute(lstm_rec_kernel, cudaFuncAttributeMaxDynamicSharedMemorySize, B_SMEM_BYTES);

    int dev = 0;
    cudaGetDevice(&dev);
    int sms = 148;
    cudaDeviceGetAttribute(&sms, cudaDevAttrMultiProcessorCount, dev);
    if (sms < 1) sms = 148;
    int agrid = (sms < A_ITEMS) ? sms : A_ITEMS;

    xg_kernel<<<agrid, A_THREADS, A_SMEM_BYTES>>>(x, Wih0);
    lstm_rec_kernel<<<NBLK, B_THREADS, B_SMEM_BYTES>>>(Whh0, Wih1, Whh1, W1, b1, W2, out);
}